// round 15
// baseline (speedup 1.0000x reference)
#include <cuda_runtime.h>
#include <math.h>

#define B_    256
#define L_    8192
#define E_    64
#define THR_  1.5f
#define SEG_  64
#define NSEG_ 128          // L_/SEG_
#define NGRP_ 16           // NSEG_/8
#define NTH_  512
#define NWARP_ 16
#define PT_   16

// token byte r of the 7-word register window (r in 0..27, constant under unroll)
#define XB(r) ((w[(r) >> 2] >> (((r) & 3) * 8)) & 15u)

__device__ __forceinline__ unsigned int packi4(int4 a) {
    return (unsigned)a.x | ((unsigned)a.y << 8) |
           ((unsigned)a.z << 16) | ((unsigned)a.w << 24);
}

// transposed cs read: position i -> owner thread, word, half. i==L_ -> slot 4096.
__device__ __forceinline__ int cs_rd(const unsigned int* c, int i) {
    int a = (i >= L_) ? (NTH_ * 8) : ((i >> 4) + NTH_ * ((i & 15) >> 1));
    unsigned int v = c[a];
    return (i & 1) ? (int)(v >> 16) : (int)(v & 0xFFFFu);
}

__global__ __launch_bounds__(NTH_, 3)
void ep_kernel(const int* __restrict__ x,
               const float* __restrict__ w1,
               const float* __restrict__ b1,
               const float* __restrict__ w2,
               const float* __restrict__ b2,
               float* __restrict__ out)
{
    __shared__ __align__(16) unsigned int csT[NTH_ * 8 + 1]; // transposed cs + total
    __shared__ unsigned short psh[NTH_];            // ps bits, 16/thread
    __shared__ unsigned char  exitt[NSEG_ * 12];
    __shared__ unsigned char  gmap1[NGRP_ * 12];
    __shared__ unsigned char  gentry[NGRP_];
    __shared__ int            hist4[4][72];         // padded: cross-warp bank spread
    __shared__ int            hist[64];
    __shared__ float          m_tab[64];
    __shared__ float          hsall[E_];
    __shared__ float          pmat[8 * 65];         // padded partials
    __shared__ float          tab[64];              // exact edge table (negated)
    __shared__ int            wsum[NWARP_];
    __shared__ int            n_sh;
    __shared__ float          extra_m;
    __shared__ int            extra_c;

    const int row  = blockIdx.x;
    const int tid  = threadIdx.x;
    const int lane = tid & 31;
    const int wid  = tid >> 5;

    const int* xrow    = x + (size_t)row * L_;
    float*     out_blt = out + (size_t)row * E_;
    float*     out_ent = out + (size_t)B_ * E_ + (size_t)row * L_;

    // ---- seed small tables; zero per-warp hists ----
    if (tid < 50) {
        int c = tid % 10, t = tid / 10 + 5;
        float p = (float)c / (float)t;
        tab[tid] = -(p * log2f(p + 1e-12f));
    } else if (tid >= 64 && tid < 64 + 62) {
        int b = tid - 64;
        m_tab[b] = (b < 13) ? ((float)b / 3.0f) : ((float)(b - 13) / 12.0f);
    } else if (tid >= 128 && tid < 128 + 288) {
        ((int*)hist4)[tid - 128] = 0;
    } else if (tid == 448) {
        extra_c = 0;
    } else if (tid == 449) {
        m_tab[62] = 0.f; m_tab[63] = 0.f;
    }

    // per-lane entropy table in registers (lane = class count 0..9)
    float f1v, dDec, dInc;
    {
        float p = (float)lane / 9.0f;
        f1v = -(p * log2f(p + 1e-12f));
        float up = __shfl_up_sync(0xffffffffu, f1v, 1);
        float dn = __shfl_down_sync(0xffffffffu, f1v, 1);
        dDec = up - f1v;      // count c -> c-1 (queried with c>=1)
        dInc = dn - f1v;      // count c -> c+1 (queried with c<=8)
    }

    // ---- x window: own 4 int4s + shuffle halo + predicated edge loads ----
    const int base = tid * PT_;
    const int4* xv = (const int4*)xrow;
    unsigned int w[7];
    {
        unsigned int W0 = packi4(xv[4 * tid + 0]);
        unsigned int W1 = packi4(xv[4 * tid + 1]);
        unsigned int W2 = packi4(xv[4 * tid + 2]);
        unsigned int W3 = packi4(xv[4 * tid + 3]);
        w[0] = __shfl_up_sync(0xffffffffu, W3, 1);
        w[5] = __shfl_down_sync(0xffffffffu, W0, 1);
        w[6] = __shfl_down_sync(0xffffffffu, W1, 1);
        if (lane == 0) {
            int wi = 4 * tid - 1; if (wi < 0) wi = 0;
            w[0] = packi4(xv[wi]);
        }
        if (lane == 31) {
            int wi5 = 4 * tid + 4; if (wi5 > L_ / 4 - 1) wi5 = L_ / 4 - 1;
            int wi6 = 4 * tid + 5; if (wi6 > L_ / 4 - 1) wi6 = L_ / 4 - 1;
            w[5] = packi4(xv[wi5]);
            w[6] = packi4(xv[wi6]);
        }
        w[1] = W0; w[2] = W1; w[3] = W2; w[4] = W3;
    }

    // ---- block scan -> exclusive prefix r at base ----
    int lsum = 0;
    #pragma unroll
    for (int k = 0; k < PT_; k++) lsum += (int)XB(k + 4);
    int v = lsum;
    #pragma unroll
    for (int d = 1; d < 32; d <<= 1) {
        int u = __shfl_up_sync(0xffffffffu, v, d);
        if (lane >= d) v += u;
    }
    if (lane == 31) wsum[wid] = v;
    __syncthreads();
    int woff = 0;
    for (int ww = 0; ww < wid; ww++) woff += wsum[ww];
    int r = woff + v - lsum;

    // ---- phase C: entropy (register deltas) + cs stores + direct ent STG ----
    unsigned int cnt = 0;
    #pragma unroll
    for (int q = 0; q < 9; q++) cnt += 1u << (XB(q) << 2);
    float S = 0.f;
    #pragma unroll
    for (int c = 0; c < 5; c++)
        S += __shfl_sync(0xffffffffu, f1v, (cnt >> (4 * c)) & 15);

    float e0 = 0.f, e1 = 0.f, e2 = 0.f;           // rotating ent buffer
    unsigned int mask = 0, cslo = 0;
    #pragma unroll
    for (int k = 0; k < PT_; k++) {
        if ((k & 1) == 0) cslo = (unsigned)r & 0xFFFFu;
        else              csT[tid + NTH_ * (k >> 1)] = cslo | ((unsigned)r << 16);
        r += (int)XB(k + 4);
        if ((k & 3) == 0)      e0 = S;
        else if ((k & 3) == 1) e1 = S;
        else if ((k & 3) == 2) e2 = S;
        else
            *(float4*)(out_ent + base + (k - 3)) = make_float4(e0, e1, e2, S);
        mask |= (S > THR_) ? (1u << k) : 0u;
        int a = (int)XB(k);
        S += __shfl_sync(0xffffffffu, dDec, (cnt >> (4 * a)) & 15);
        cnt -= 1u << (4 * a);
        int b = (int)XB(k + 9);
        S += __shfl_sync(0xffffffffu, dInc, (cnt >> (4 * b)) & 15);
        cnt += 1u << (4 * b);
    }
    if (tid == NTH_ - 1) csT[NTH_ * 8] = (unsigned)r & 0xFFFFu;   // row total

    // ---- row-edge fixups (t<9): exact recompute, overwrite gmem + mask ----
    if (tid == 0) {
        float ef[4];
        #pragma unroll
        for (int k = 0; k < 4; k++) {       // positions 0..3, window [0, k+4]
            unsigned int c = 0;
            #pragma unroll
            for (int rr = 4; rr <= 12; rr++)
                if (rr <= k + 8) c += 1u << (XB(rr) << 2);
            int t = k + 5;
            const float* tb = &tab[(t - 5) * 10];
            float e = tb[c & 15] + tb[(c >> 4) & 15] + tb[(c >> 8) & 15] +
                      tb[(c >> 12) & 15] + tb[(c >> 16) & 15];
            ef[k] = e;
            mask = (mask & ~(1u << k)) | ((e > THR_) ? (1u << k) : 0u);
        }
        *(float4*)(out_ent) = make_float4(ef[0], ef[1], ef[2], ef[3]);
    }
    if (tid == NTH_ - 1) {
        float ef[4];
        #pragma unroll
        for (int k = 12; k < 16; k++) {     // positions 8188..8191
            unsigned int c = 0;
            #pragma unroll
            for (int rr = 12; rr <= 19; rr++)
                if (rr >= k) c += 1u << (XB(rr) << 2);
            int t = 20 - k;
            const float* tb = &tab[(t - 5) * 10];
            float e = tb[c & 15] + tb[(c >> 4) & 15] + tb[(c >> 8) & 15] +
                      tb[(c >> 12) & 15] + tb[(c >> 16) & 15];
            ef[k - 12] = e;
            mask = (mask & ~(1u << k)) | ((e > THR_) ? (1u << k) : 0u);
        }
        *(float4*)(out_ent + L_ - 4) = make_float4(ef[0], ef[1], ef[2], ef[3]);
    }

    psh[tid] = (unsigned short)mask;
    __syncthreads();

    const unsigned int* psw = (const unsigned int*)psh;   // word m = positions 32m..32m+31

    // ---- phase 4: (seg, entry) exits via register-bit walks; 3 tasks/thread ----
    {
        int t0 = tid, t1 = tid + NTH_, t2 = tid + 2 * NTH_;
        int s0 = t0 / 12, s1 = t1 / 12, s2 = t2 / 12;
        unsigned int a0 = psw[2 * s0], b0 = psw[2 * s0 + 1];
        unsigned int a1 = psw[2 * s1], b1w = psw[2 * s1 + 1];
        unsigned int a2 = psw[2 * s2], b2w = psw[2 * s2 + 1];
        int p0 = t0 % 12, p1 = t1 % 12, p2 = t2 % 12;
        while (p0 < SEG_ || p1 < SEG_ || p2 < SEG_) {
            if (p0 < SEG_) {
                unsigned int ws = (p0 < 32) ? a0 : b0;
                p0 += ((ws >> (p0 & 31)) & 1u) ? 3 : 12;
            }
            if (p1 < SEG_) {
                unsigned int ws = (p1 < 32) ? a1 : b1w;
                p1 += ((ws >> (p1 & 31)) & 1u) ? 3 : 12;
            }
            if (p2 < SEG_) {
                unsigned int ws = (p2 < 32) ? a2 : b2w;
                p2 += ((ws >> (p2 & 31)) & 1u) ? 3 : 12;
            }
        }
        exitt[t0] = (unsigned char)(p0 - SEG_);
        exitt[t1] = (unsigned char)(p1 - SEG_);
        exitt[t2] = (unsigned char)(p2 - SEG_);
    }
    __syncthreads();

    // ---- compose: 16 groups of 8 segs x 12 entries ----
    if (tid < NGRP_ * 12) {
        int g = tid / 12, e = tid % 12;
        int c = e;
        #pragma unroll
        for (int i = 0; i < 8; i++) c = exitt[(g * 8 + i) * 12 + c];
        gmap1[tid] = (unsigned char)c;
    }
    __syncthreads();

    // ---- serial 16-link compose (thread 0) ----
    if (tid == 0) {
        int e = 0;
        #pragma unroll
        for (int g = 0; g < NGRP_; g++) {
            gentry[g] = (unsigned char)e;
            e = gmap1[g * 12 + e];
        }
    }
    __syncthreads();

    // ---- phase 6: 128 walkers; match_any-aggregated histograms ----
    if (tid < NSEG_) {
        int g = tid >> 3;
        int c = gentry[g];
        for (int i = g * 8; i < tid; i++) c = exitt[i * 12 + c];
        unsigned int a0 = psw[2 * tid], a1 = psw[2 * tid + 1];
        int p = c;
        int gb = tid * SEG_;
        int csnow = cs_rd(csT, gb + p);
        int* myh = hist4[tid >> 5];
        while (__any_sync(0xffffffffu, p < SEG_)) {
            bool active = (p < SEG_);
            int  bin = 64 + lane;            // unique dummy, never written
            bool wr  = false;
            if (active) {
                unsigned int ws = (p < 32) ? a0 : a1;
                int bit = (ws >> (p & 31)) & 1;
                int psz = bit ? 3 : 12;
                int gj  = gb + p + psz;
                if (gj > L_) {               // truncated final patch
                    int sum = cs_rd(csT, L_) - csnow;
                    extra_m = (float)sum / (float)(L_ - (gb + p));
                    extra_c = 1;
                    p = SEG_;
                } else {
                    int csj = cs_rd(csT, gj);
                    bin = bit ? (csj - csnow) : (13 + csj - csnow);   // 0..61
                    csnow = csj;
                    p += psz;
                    wr = true;
                }
            }
            unsigned grp = __match_any_sync(0xffffffffu, bin);
            if (wr) {
                int leader = __ffs((int)grp) - 1;
                if (lane == leader) myh[bin] += __popc(grp);
            }
        }
    }
    __syncthreads();

    // ---- reduce per-warp histograms; n via warp 2 ----
    if (tid < 64)
        hist[tid] = (tid < 62) ? (hist4[0][tid] + hist4[1][tid] +
                                  hist4[2][tid] + hist4[3][tid]) : 0;
    __syncthreads();
    if (wid == 2) {
        int vv = hist[lane] + hist[lane + 32];
        #pragma unroll
        for (int d = 16; d > 0; d >>= 1) vv += __shfl_xor_sync(0xffffffffu, vv, d);
        if (lane == 0) n_sh = vv;
    }

    // ---- relu expansion partials: thread (mc, mg) covers 8 bins ----
    const int mc = tid >> 3;          // channel 0..63
    const int mg = tid & 7;           // j-group 0..7
    {
        float w1c = __ldg(&w1[mc]), b1c = __ldg(&b1[mc]);
        float ph = 0.f;
        #pragma unroll
        for (int jj = 0; jj < 8; jj++) {
            int b = mg * 8 + jj;
            ph += (float)hist[b] * fmaxf(fmaf(m_tab[b], w1c, b1c), 0.f);
        }
        pmat[mg * 65 + mc] = ph;
    }
    __syncthreads();

    // ---- hsall combine (+ truncated-patch term) ----
    if (tid < E_) {
        float hs = 0.f;
        #pragma unroll
        for (int g = 0; g < 8; g++) hs += pmat[g * 65 + tid];
        if (extra_c)
            hs += fmaxf(fmaf(extra_m, __ldg(&w1[tid]), __ldg(&b1[tid])), 0.f);
        hsall[tid] = hs;
    }
    __syncthreads();

    // ---- matvec partials ----
    {
        const float* w2p = w2 + mc * E_ + mg * 8;
        float acc = 0.f;
        #pragma unroll
        for (int jj = 0; jj < 8; jj++) acc += hsall[mg * 8 + jj] * __ldg(&w2p[jj]);
        pmat[mg * 65 + mc] = acc;
    }
    __syncthreads();

    if (tid < E_) {
        float acc = 0.f;
        #pragma unroll
        for (int g = 0; g < 8; g++) acc += pmat[g * 65 + tid];
        int n = n_sh + extra_c;
        out_blt[tid] = acc / (float)n + b2[tid];
    }
}

extern "C" void kernel_launch(void* const* d_in, const int* in_sizes, int n_in,
                              void* d_out, int out_size)
{
    const int*   x  = (const int*)d_in[0];
    const float* w1 = (const float*)d_in[1];
    const float* b1 = (const float*)d_in[2];
    const float* w2 = (const float*)d_in[3];
    const float* b2 = (const float*)d_in[4];
    ep_kernel<<<B_, NTH_>>>(x, w1, b1, w2, b2, (float*)d_out);
}

// round 16
// speedup vs baseline: 1.0861x; 1.0861x over previous
#include <cuda_runtime.h>
#include <math.h>

#define B_    256
#define L_    8192
#define E_    64
#define THR_  1.5f
#define SEG_  64
#define NSEG_ 128          // L_/SEG_
#define NGRP_ 16           // NSEG_/8
#define NTH_  512
#define NWARP_ 16
#define PT_   16

// token byte r of the 7-word register window (r in 0..27, constant under unroll)
#define XB(r) ((w[(r) >> 2] >> (((r) & 3) * 8)) & 15u)

__device__ __forceinline__ unsigned int packi4(int4 a) {
    return (unsigned)a.x | ((unsigned)a.y << 8) |
           ((unsigned)a.z << 16) | ((unsigned)a.w << 24);
}

// transposed cs read: position i -> owner thread, word, half. i==L_ -> slot 4096.
__device__ __forceinline__ int cs_rd(const unsigned int* c, int i) {
    int a = (i >= L_) ? (NTH_ * 8) : ((i >> 4) + NTH_ * ((i & 15) >> 1));
    unsigned int v = c[a];
    return (i & 1) ? (int)(v >> 16) : (int)(v & 0xFFFFu);
}

// mod-3 class mask over a 32-bit word whose bit 0 has class base c
__device__ __forceinline__ unsigned int class_mask(int c) {
    return (c == 0) ? 0x49249249u : (c == 1) ? 0x92492492u : 0x24924924u;
}

__global__ __launch_bounds__(NTH_, 2)
void ep_kernel(const int* __restrict__ x,
               const float* __restrict__ w1,
               const float* __restrict__ b1,
               const float* __restrict__ w2,
               const float* __restrict__ b2,
               float* __restrict__ out)
{
    __shared__ __align__(16) unsigned int csT[NTH_ * 8 + 1]; // transposed cs + total
    __shared__ unsigned short psh[NTH_];            // ps bits, 16/thread
    __shared__ unsigned char  exitt[NSEG_ * 12];
    __shared__ unsigned char  gmap1[NGRP_ * 12];
    __shared__ unsigned char  gentry[NGRP_];
    __shared__ int            hist4[4][72];         // padded: cross-warp bank spread
    __shared__ int            hist[64];
    __shared__ float          m_tab[64];
    __shared__ float          hsall[E_];
    __shared__ float          pmat[8 * 65];         // padded partials
    __shared__ float          tab[64];              // exact edge table (negated)
    __shared__ int            wsum[NWARP_];
    __shared__ int            n_sh;
    __shared__ float          extra_m;
    __shared__ int            extra_c;

    const int row  = blockIdx.x;
    const int tid  = threadIdx.x;
    const int lane = tid & 31;
    const int wid  = tid >> 5;

    const int* xrow    = x + (size_t)row * L_;
    float*     out_blt = out + (size_t)row * E_;
    float*     out_ent = out + (size_t)B_ * E_ + (size_t)row * L_;

    // ---- seed small tables; zero per-warp hists ----
    if (tid < 50) {
        int c = tid % 10, t = tid / 10 + 5;
        float p = (float)c / (float)t;
        tab[tid] = -(p * log2f(p + 1e-12f));
    } else if (tid >= 64 && tid < 64 + 62) {
        int b = tid - 64;
        m_tab[b] = (b < 13) ? ((float)b / 3.0f) : ((float)(b - 13) / 12.0f);
    } else if (tid >= 128 && tid < 128 + 288) {
        ((int*)hist4)[tid - 128] = 0;
    } else if (tid == 448) {
        extra_c = 0;
    } else if (tid == 449) {
        m_tab[62] = 0.f; m_tab[63] = 0.f;
    }

    // per-lane entropy table in registers (lane = class count 0..9)
    float f1v, dDec, dInc;
    {
        float p = (float)lane / 9.0f;
        f1v = -(p * log2f(p + 1e-12f));
        float up = __shfl_up_sync(0xffffffffu, f1v, 1);
        float dn = __shfl_down_sync(0xffffffffu, f1v, 1);
        dDec = up - f1v;      // count c -> c-1 (queried with c>=1)
        dInc = dn - f1v;      // count c -> c+1 (queried with c<=8)
    }

    // ---- x window: own 4 int4s + shuffle halo + predicated edge loads ----
    const int base = tid * PT_;
    const int4* xv = (const int4*)xrow;
    unsigned int w[7];
    {
        unsigned int W0 = packi4(xv[4 * tid + 0]);
        unsigned int W1 = packi4(xv[4 * tid + 1]);
        unsigned int W2 = packi4(xv[4 * tid + 2]);
        unsigned int W3 = packi4(xv[4 * tid + 3]);
        w[0] = __shfl_up_sync(0xffffffffu, W3, 1);
        w[5] = __shfl_down_sync(0xffffffffu, W0, 1);
        w[6] = __shfl_down_sync(0xffffffffu, W1, 1);
        if (lane == 0) {
            int wi = 4 * tid - 1; if (wi < 0) wi = 0;
            w[0] = packi4(xv[wi]);
        }
        if (lane == 31) {
            int wi5 = 4 * tid + 4; if (wi5 > L_ / 4 - 1) wi5 = L_ / 4 - 1;
            int wi6 = 4 * tid + 5; if (wi6 > L_ / 4 - 1) wi6 = L_ / 4 - 1;
            w[5] = packi4(xv[wi5]);
            w[6] = packi4(xv[wi6]);
        }
        w[1] = W0; w[2] = W1; w[3] = W2; w[4] = W3;
    }

    // ---- block scan -> exclusive prefix r at base ----
    int lsum = 0;
    #pragma unroll
    for (int k = 0; k < PT_; k++) lsum += (int)XB(k + 4);
    int v = lsum;
    #pragma unroll
    for (int d = 1; d < 32; d <<= 1) {
        int u = __shfl_up_sync(0xffffffffu, v, d);
        if (lane >= d) v += u;
    }
    if (lane == 31) wsum[wid] = v;
    __syncthreads();
    int woff = 0;
    for (int ww = 0; ww < wid; ww++) woff += wsum[ww];
    int r = woff + v - lsum;

    // ---- phase C: entropy (register deltas) + transposed cs stores ----
    unsigned int cnt = 0;
    #pragma unroll
    for (int q = 0; q < 9; q++) cnt += 1u << (XB(q) << 2);
    float S = 0.f;
    #pragma unroll
    for (int c = 0; c < 5; c++)
        S += __shfl_sync(0xffffffffu, f1v, (cnt >> (4 * c)) & 15);

    float entv[PT_];
    unsigned int mask = 0, cslo = 0;
    #pragma unroll
    for (int k = 0; k < PT_; k++) {
        if ((k & 1) == 0) cslo = (unsigned)r & 0xFFFFu;
        else              csT[tid + NTH_ * (k >> 1)] = cslo | ((unsigned)r << 16);
        r += (int)XB(k + 4);
        entv[k] = S;
        mask |= (S > THR_) ? (1u << k) : 0u;
        int a = (int)XB(k);
        S += __shfl_sync(0xffffffffu, dDec, (cnt >> (4 * a)) & 15);
        cnt -= 1u << (4 * a);
        int b = (int)XB(k + 9);
        S += __shfl_sync(0xffffffffu, dInc, (cnt >> (4 * b)) & 15);
        cnt += 1u << (4 * b);
    }
    if (tid == NTH_ - 1) csT[NTH_ * 8] = (unsigned)r & 0xFFFFu;   // row total

    // ---- row-edge fixups (t<9), in-register, exact table ----
    if (tid == 0) {
        #pragma unroll
        for (int k = 0; k < 4; k++) {       // positions 0..3, window [0, k+4]
            unsigned int c = 0;
            #pragma unroll
            for (int rr = 4; rr <= 12; rr++)
                if (rr <= k + 8) c += 1u << (XB(rr) << 2);
            int t = k + 5;
            const float* tb = &tab[(t - 5) * 10];
            float e = tb[c & 15] + tb[(c >> 4) & 15] + tb[(c >> 8) & 15] +
                      tb[(c >> 12) & 15] + tb[(c >> 16) & 15];
            entv[k] = e;
            mask = (mask & ~(1u << k)) | ((e > THR_) ? (1u << k) : 0u);
        }
    }
    if (tid == NTH_ - 1) {
        #pragma unroll
        for (int k = 12; k < 16; k++) {     // positions 8188..8191, window [i-4, L-1]
            unsigned int c = 0;
            #pragma unroll
            for (int rr = 12; rr <= 19; rr++)
                if (rr >= k) c += 1u << (XB(rr) << 2);
            int t = 20 - k;
            const float* tb = &tab[(t - 5) * 10];
            float e = tb[c & 15] + tb[(c >> 4) & 15] + tb[(c >> 8) & 15] +
                      tb[(c >> 12) & 15] + tb[(c >> 16) & 15];
            entv[k] = e;
            mask = (mask & ~(1u << k)) | ((e > THR_) ? (1u << k) : 0u);
        }
    }

    // ---- store ps bits + entropy direct to gmem ----
    psh[tid] = (unsigned short)mask;
    {
        float4* eo = (float4*)(out_ent + base);
        eo[0] = make_float4(entv[0],  entv[1],  entv[2],  entv[3]);
        eo[1] = make_float4(entv[4],  entv[5],  entv[6],  entv[7]);
        eo[2] = make_float4(entv[8],  entv[9],  entv[10], entv[11]);
        eo[3] = make_float4(entv[12], entv[13], entv[14], entv[15]);
    }
    __syncthreads();

    const unsigned int* psw = (const unsigned int*)psh;   // word m = positions 32m..32m+31

    // ---- phase 4: FFS-based exits (jumps preserve p mod 3); 3 tasks/thread ----
    {
        #pragma unroll
        for (int it = 0; it < 3; it++) {
            int task = tid + it * NTH_;
            int sg = task / 12, e = task % 12;
            unsigned int a0 = psw[2 * sg], a1 = psw[2 * sg + 1];
            int c = e % 3;
            // word1 bit 0 is position 32; 32 mod 3 = 2, so its class base is (c+1)%3
            unsigned int inv0 = ~a0 & class_mask(c);
            unsigned int inv1 = ~a1 & class_mask((c + 1) % 3);
            int p = e;
            while (p < SEG_) {
                unsigned int t0 = (p < 32) ? (inv0 & (0xFFFFFFFFu << p)) : 0u;
                unsigned int t1 = (p < 32) ? inv1
                                           : (inv1 & (0xFFFFFFFFu << (p - 32)));
                int z = t0 ? (__ffs(t0) - 1) : (t1 ? (31 + __ffs(t1)) : -1);
                if (z < 0) {                 // all class bits >= p are 1: 3-jump out
                    int d = SEG_ - p;
                    p += ((d + 2) / 3) * 3;
                    break;
                }
                p = z + 12;                  // 3-jumps to z (first zero), then 12-jump
            }
            exitt[task] = (unsigned char)(p - SEG_);
        }
    }
    __syncthreads();

    // ---- compose: 16 groups of 8 segs x 12 entries ----
    if (tid < NGRP_ * 12) {
        int g = tid / 12, e = tid % 12;
        int c = e;
        #pragma unroll
        for (int i = 0; i < 8; i++) c = exitt[(g * 8 + i) * 12 + c];
        gmap1[tid] = (unsigned char)c;
    }
    __syncthreads();

    // ---- serial 16-link compose (thread 0) ----
    if (tid == 0) {
        int e = 0;
        #pragma unroll
        for (int g = 0; g < NGRP_; g++) {
            gentry[g] = (unsigned char)e;
            e = gmap1[g * 12 + e];
        }
    }
    __syncthreads();

    // ---- w2 preload (all threads; latency hidden behind phase 6) ----
    const int mc = tid >> 3;          // channel 0..63
    const int mg = tid & 7;           // j-group 0..7
    float w2r[8];
    {
        const float4* wv = (const float4*)(w2 + mc * E_ + mg * 8);
        float4 aa = wv[0], bb = wv[1];
        w2r[0] = aa.x; w2r[1] = aa.y; w2r[2] = aa.z; w2r[3] = aa.w;
        w2r[4] = bb.x; w2r[5] = bb.y; w2r[6] = bb.z; w2r[7] = bb.w;
    }

    // ---- phase 6: 128 walkers; match_any-aggregated histograms ----
    if (tid < NSEG_) {
        int g = tid >> 3;
        int c = gentry[g];
        for (int i = g * 8; i < tid; i++) c = exitt[i * 12 + c];
        unsigned int a0 = psw[2 * tid], a1 = psw[2 * tid + 1];
        int p = c;
        int gb = tid * SEG_;
        int csnow = cs_rd(csT, gb + p);
        int* myh = hist4[tid >> 5];
        while (__any_sync(0xffffffffu, p < SEG_)) {
            bool active = (p < SEG_);
            int  bin = 64 + lane;            // unique dummy, never written
            bool wr  = false;
            if (active) {
                unsigned int ws = (p < 32) ? a0 : a1;
                int bit = (ws >> (p & 31)) & 1;
                int psz = bit ? 3 : 12;
                int gj  = gb + p + psz;
                if (gj > L_) {               // truncated final patch
                    int sum = cs_rd(csT, L_) - csnow;
                    extra_m = (float)sum / (float)(L_ - (gb + p));
                    extra_c = 1;
                    p = SEG_;
                } else {
                    int csj = cs_rd(csT, gj);
                    bin = bit ? (csj - csnow) : (13 + csj - csnow);   // 0..61
                    csnow = csj;
                    p += psz;
                    wr = true;
                }
            }
            unsigned grp = __match_any_sync(0xffffffffu, bin);
            if (wr) {
                int leader = __ffs((int)grp) - 1;
                if (lane == leader) myh[bin] += __popc(grp);
            }
        }
    }
    __syncthreads();

    // ---- reduce per-warp histograms; n via warp 2 ----
    if (tid < 64)
        hist[tid] = (tid < 62) ? (hist4[0][tid] + hist4[1][tid] +
                                  hist4[2][tid] + hist4[3][tid]) : 0;
    __syncthreads();
    if (wid == 2) {
        int vv = hist[lane] + hist[lane + 32];
        #pragma unroll
        for (int d = 16; d > 0; d >>= 1) vv += __shfl_xor_sync(0xffffffffu, vv, d);
        if (lane == 0) n_sh = vv;
    }

    // ---- relu expansion partials: thread (mc, mg) covers 8 bins ----
    {
        float w1c = __ldg(&w1[mc]), b1c = __ldg(&b1[mc]);
        float ph = 0.f;
        #pragma unroll
        for (int jj = 0; jj < 8; jj++) {
            int b = mg * 8 + jj;
            ph += (float)hist[b] * fmaxf(fmaf(m_tab[b], w1c, b1c), 0.f);
        }
        pmat[mg * 65 + mc] = ph;
    }
    __syncthreads();

    // ---- hsall combine (+ truncated-patch term) ----
    if (tid < E_) {
        float hs = 0.f;
        #pragma unroll
        for (int g = 0; g < 8; g++) hs += pmat[g * 65 + tid];
        if (extra_c)
            hs += fmaxf(fmaf(extra_m, __ldg(&w1[tid]), __ldg(&b1[tid])), 0.f);
        hsall[tid] = hs;
    }
    __syncthreads();

    // ---- matvec partials with preloaded w2 ----
    {
        float acc = 0.f;
        #pragma unroll
        for (int jj = 0; jj < 8; jj++) acc += hsall[mg * 8 + jj] * w2r[jj];
        pmat[mg * 65 + mc] = acc;
    }
    __syncthreads();

    if (tid < E_) {
        float acc = 0.f;
        #pragma unroll
        for (int g = 0; g < 8; g++) acc += pmat[g * 65 + tid];
        int n = n_sh + extra_c;
        out_blt[tid] = acc / (float)n + b2[tid];
    }
}

extern "C" void kernel_launch(void* const* d_in, const int* in_sizes, int n_in,
                              void* d_out, int out_size)
{
    const int*   x  = (const int*)d_in[0];
    const float* w1 = (const float*)d_in[1];
    const float* b1 = (const float*)d_in[2];
    const float* w2 = (const float*)d_in[3];
    const float* b2 = (const float*)d_in[4];
    ep_kernel<<<B_, NTH_>>>(x, w1, b1, w2, b2, (float*)d_out);
}